// round 3
// baseline (speedup 1.0000x reference)
#include <cuda_runtime.h>
#include <cstdint>

// out[s,:] = W_tok[x[s],:] + b_tok + W_pos[(S-1)-s,:] + b_pos
// S=8192, D=1024 fp32 (4 KB rows).
// R3: cp.async.bulk (TMA path) gathers rows into SMEM -> decouples memory
// parallelism from the register file (R2 showed MLP/occupancy coupling with
// nothing saturated: DRAM 53.8%, issue 12.8%).

constexpr int SEQ       = 8192;
constexpr int EMBED     = 1024;
constexpr int VEC       = EMBED / 4;      // 256 float4 per row
constexpr int ROWS      = 4;              // rows per CTA (= pipeline stages)
constexpr int ROW_BYTES = EMBED * 4;      // 4096

__device__ __forceinline__ uint32_t smem_u32(const void* p) {
    return (uint32_t)__cvta_generic_to_shared(p);
}

__device__ __forceinline__ void mbar_init(uint32_t mbar, uint32_t count) {
    asm volatile("mbarrier.init.shared.b64 [%0], %1;" :: "r"(mbar), "r"(count) : "memory");
}

__device__ __forceinline__ void mbar_expect_tx(uint32_t mbar, uint32_t bytes) {
    asm volatile("mbarrier.arrive.expect_tx.shared.b64 _, [%0], %1;"
                 :: "r"(mbar), "r"(bytes) : "memory");
}

__device__ __forceinline__ void bulk_g2s(uint32_t dst_smem, const void* src_gmem,
                                         uint32_t bytes, uint32_t mbar) {
    asm volatile(
        "cp.async.bulk.shared::cta.global.mbarrier::complete_tx::bytes "
        "[%0], [%1], %2, [%3];"
        :: "r"(dst_smem), "l"(src_gmem), "r"(bytes), "r"(mbar) : "memory");
}

__device__ __forceinline__ void mbar_wait(uint32_t mbar, uint32_t parity) {
    asm volatile(
        "{\n\t"
        ".reg .pred P;\n\t"
        "WAIT_%=:\n\t"
        "mbarrier.try_wait.parity.acquire.cta.shared::cta.b64 P, [%0], %1, 0x989680;\n\t"
        "@P bra.uni DONE_%=;\n\t"
        "bra.uni WAIT_%=;\n\t"
        "DONE_%=:\n\t"
        "}"
        :: "r"(mbar), "r"(parity) : "memory");
}

__global__ __launch_bounds__(256)
void linear_embedding_tma(const int* __restrict__ x,
                          const float* __restrict__ W_tok,
                          const float4* __restrict__ b_tok,
                          const float* __restrict__ W_pos,
                          const float4* __restrict__ b_pos,
                          float4* __restrict__ out)
{
    __shared__ alignas(128) float tok_buf[ROWS][EMBED];   // 16 KB
    __shared__ alignas(128) float pos_buf[ROWS][EMBED];   // 16 KB
    __shared__ alignas(8)   uint64_t full_bar[ROWS];

    const int t  = threadIdx.x;
    const int s0 = blockIdx.x * ROWS;

    if (t == 0) {
#pragma unroll
        for (int i = 0; i < ROWS; ++i)
            mbar_init(smem_u32(&full_bar[i]), 1);
    }
    __syncthreads();

    if (t == 0) {
        // Token ids for this CTA's rows, then 8 independent 4KB bulk copies.
        int tok[ROWS];
#pragma unroll
        for (int i = 0; i < ROWS; ++i)
            tok[i] = __ldg(&x[s0 + i]);
#pragma unroll
        for (int i = 0; i < ROWS; ++i) {
            uint32_t mb = smem_u32(&full_bar[i]);
            mbar_expect_tx(mb, 2 * ROW_BYTES);
            bulk_g2s(smem_u32(&tok_buf[i][0]),
                     W_tok + (long long)tok[i] * EMBED, ROW_BYTES, mb);
            bulk_g2s(smem_u32(&pos_buf[i][0]),
                     W_pos + (long long)(SEQ - 1 - (s0 + i)) * EMBED, ROW_BYTES, mb);
        }
    }

    // Biases (zero in practice; L2-resident). Overlaps with TMA in flight.
    const float4 bt = __ldg(&b_tok[t]);
    const float4 bp = __ldg(&b_pos[t]);
    float4 b;
    b.x = bt.x + bp.x; b.y = bt.y + bp.y;
    b.z = bt.z + bp.z; b.w = bt.w + bp.w;

    const float4* tokb = (const float4*)tok_buf;
    const float4* posb = (const float4*)pos_buf;

#pragma unroll
    for (int i = 0; i < ROWS; ++i) {
        mbar_wait(smem_u32(&full_bar[i]), 0);
        float4 a = tokb[i * VEC + t];
        float4 p = posb[i * VEC + t];
        float4 r;
        r.x = (a.x + p.x) + b.x;
        r.y = (a.y + p.y) + b.y;
        r.z = (a.z + p.z) + b.z;
        r.w = (a.w + p.w) + b.w;
        out[(long long)(s0 + i) * VEC + t] = r;
    }
}

extern "C" void kernel_launch(void* const* d_in, const int* in_sizes, int n_in,
                              void* d_out, int out_size)
{
    const int*    x     = (const int*)d_in[0];
    const float*  W_tok = (const float*)d_in[1];
    const float4* b_tok = (const float4*)d_in[2];
    const float*  W_pos = (const float*)d_in[3];
    const float4* b_pos = (const float4*)d_in[4];
    float4* out = (float4*)d_out;

    linear_embedding_tma<<<SEQ / ROWS, 256>>>(x, W_tok, b_tok, W_pos, b_pos, out);
}